// round 15
// baseline (speedup 1.0000x reference)
#include <cuda_runtime.h>
#include <cuda_fp16.h>
#include <cstdint>
#include <cfloat>

#define N_NODES 50000
#define N_EDGES 800000
#define IN_DIM  256
#define HEADS   4
#define OUT_DIM 64
#define FDIM    256            // HEADS * OUT_DIM
#define ALPHA   0.2f

#define SCAN_TPB 256
#define SCAN_NB  ((N_NODES + SCAN_TPB - 1) / SCAN_TPB)   // 196

// ---------------- scratch (static device globals; no allocation) -------------
__device__ __half g_fth[N_NODES * FDIM];     // projected features, fp16 [N,256]
__device__ __half g_Wh [FDIM * IN_DIM];      // W pre-converted to fp16 [256,256]
__device__ float  g_a1 [N_NODES * HEADS];    // src-side attn term [N,4]
__device__ float  g_a2 [N_NODES * HEADS];    // dst-side attn term [N,4]
__device__ int    g_deg     [N_NODES];       // in-degree histogram (self-resetting)
__device__ int    g_rowstart[N_NODES + 1];   // CSR row offsets (by dst)
__device__ int    g_cursor  [N_NODES];       // scatter cursors
__device__ int    g_csr_src [N_EDGES];       // CSR payload: src node per slot
__device__ int    g_bsum [SCAN_NB];          // scan block sums

// ---------------- 0) W -> fp16 conversion (once per launch, deterministic) ---
__global__ void wconv_kernel(const float* __restrict__ Wm) {
    int i = (blockIdx.x * blockDim.x + threadIdx.x) * 4;
    if (i < FDIM * IN_DIM) {
        float4 v = *reinterpret_cast<const float4*>(Wm + i);
        __half2 a = __floats2half2_rn(v.x, v.y);
        __half2 b = __floats2half2_rn(v.z, v.w);
        *reinterpret_cast<uint2*>(g_Wh + i) =
            make_uint2(reinterpret_cast<uint32_t&>(a),
                       reinterpret_cast<uint32_t&>(b));
    }
}

// ---------------- 1) GEMM (fp16 split-A, GBM=64 for 2 blocks/SM) + a1a2 ------
#define GBM 64
#define GBN 256
#define GBK 32
#define LDT 40   // padded fp16 row stride: 80B rows, 16B-aligned 8x8 tiles

__device__ __forceinline__ void split2h(float a, float b,
                                        uint32_t& hi, uint32_t& lo) {
    __half2 hp = __floats2half2_rn(a, b);
    hi = reinterpret_cast<uint32_t&>(hp);
    __half2 lp = __floats2half2_rn(a - __half2float(__low2half(hp)),
                                   b - __half2float(__high2half(hp)));
    lo = reinterpret_cast<uint32_t&>(lp);
}

__device__ __forceinline__ void mma_f16(float c[4],
                                        const uint32_t a[4],
                                        const uint32_t b0, const uint32_t b1) {
    asm volatile(
        "mma.sync.aligned.m16n8k16.row.col.f32.f16.f16.f32 "
        "{%0,%1,%2,%3}, {%4,%5,%6,%7}, {%8,%9}, {%0,%1,%2,%3};\n"
        : "+f"(c[0]), "+f"(c[1]), "+f"(c[2]), "+f"(c[3])
        : "r"(a[0]), "r"(a[1]), "r"(a[2]), "r"(a[3]), "r"(b0), "r"(b1));
}

__device__ __forceinline__ void ldsm_x4(uint32_t r[4], uint32_t addr) {
    asm volatile(
        "ldmatrix.sync.aligned.m8n8.x4.shared.b16 {%0,%1,%2,%3}, [%4];"
        : "=r"(r[0]), "=r"(r[1]), "=r"(r[2]), "=r"(r[3]) : "r"(addr));
}

__global__ __launch_bounds__(256, 2)
void gemm_f16x2_kernel(const float* __restrict__ A,
                       const float* __restrict__ attn_l,
                       const float* __restrict__ attn_r)
{
    __shared__ __half Ah[GBM * LDT], Al[GBM * LDT];
    __shared__ __half Bh[GBN * LDT];

    const int tid  = threadIdx.x;
    const int warp = tid >> 5, lane = tid & 31;
    const int g = lane >> 2, t = lane & 3;
    const int warp_m = warp >> 1;          // 0..3 (16 M-rows each)
    const int warp_n = warp & 1;           // 0..1 (128 N-cols each)
    const int block_row = blockIdx.x * GBM;

    float acc[16][4];
#pragma unroll
    for (int ni = 0; ni < 16; ni++)
#pragma unroll
        for (int i = 0; i < 4; i++) acc[ni][i] = 0.0f;

    const int lrow = tid >> 2;             // A row 0..63
    const int lk0  = (tid & 3) * 8;        // A k-slice 0,8,16,24
    const int ar   = block_row + lrow;
    const bool aok = (ar < N_NODES);
    const int br   = tid;                  // B row 0..255 (full W)

    const uint32_t ah_base = (uint32_t)__cvta_generic_to_shared(Ah);
    const uint32_t al_base = (uint32_t)__cvta_generic_to_shared(Al);
    const uint32_t bh_base = (uint32_t)__cvta_generic_to_shared(Bh);
    const uint32_t a_off = 2u * ((uint32_t)(warp_m * 16 + (lane & 15)) * LDT
                                 + (uint32_t)((lane >> 4) * 8));
    const uint32_t b_off = 2u * ((uint32_t)(warp_n * 128 + ((lane >> 4) << 3)
                                            + (lane & 7)) * LDT
                                 + (uint32_t)(((lane >> 3) & 1) << 3));

    float4 pa[2];
    uint4  pbv[4];
#pragma unroll
    for (int q = 0; q < 2; q++) {
        int ko = lk0 + q * 4;
        pa[q] = aok ? *reinterpret_cast<const float4*>(A + (size_t)ar * IN_DIM + ko)
                    : make_float4(0.f, 0.f, 0.f, 0.f);
    }
#pragma unroll
    for (int q = 0; q < 4; q++) {
        pbv[q] = *reinterpret_cast<const uint4*>(g_Wh + (size_t)br * IN_DIM + q * 8);
    }

    for (int k0 = 0; k0 < IN_DIM; k0 += GBK) {
        // ---- split A + copy B into smem ----
#pragma unroll
        for (int q = 0; q < 2; q++) {
            int ko = lk0 + q * 4;
            uint32_t h01, l01, h23, l23;
            split2h(pa[q].x, pa[q].y, h01, l01);
            split2h(pa[q].z, pa[q].w, h23, l23);
            *reinterpret_cast<uint2*>(&Ah[lrow * LDT + ko]) = make_uint2(h01, h23);
            *reinterpret_cast<uint2*>(&Al[lrow * LDT + ko]) = make_uint2(l01, l23);
        }
#pragma unroll
        for (int q = 0; q < 4; q++) {
            *reinterpret_cast<uint4*>(&Bh[br * LDT + q * 8]) = pbv[q];
        }
        __syncthreads();

        // ---- prefetch next tile ----
        int kn = k0 + GBK;
        if (kn < IN_DIM) {
#pragma unroll
            for (int q = 0; q < 2; q++) {
                int ko = kn + lk0 + q * 4;
                pa[q] = aok ? *reinterpret_cast<const float4*>(
                                  A + (size_t)ar * IN_DIM + ko)
                            : make_float4(0.f, 0.f, 0.f, 0.f);
            }
#pragma unroll
            for (int q = 0; q < 4; q++) {
                pbv[q] = *reinterpret_cast<const uint4*>(
                             g_Wh + (size_t)br * IN_DIM + kn + q * 8);
            }
        }

        // ---- MMA compute (ldmatrix fragments) ----
#pragma unroll
        for (int kk = 0; kk < GBK; kk += 16) {
            uint32_t ah[4], al[4];
            ldsm_x4(ah, ah_base + a_off + 2 * kk);
            ldsm_x4(al, al_base + a_off + 2 * kk);
#pragma unroll
            for (int p = 0; p < 8; p++) {        // 16 ni as 8 pairs
                uint32_t bb[4];
                ldsm_x4(bb, bh_base + b_off + 2 * (p * 16 * LDT + kk));
                mma_f16(acc[2 * p],     ah, bb[0], bb[1]);
                mma_f16(acc[2 * p],     al, bb[0], bb[1]);
                mma_f16(acc[2 * p + 1], ah, bb[2], bb[3]);
                mma_f16(acc[2 * p + 1], al, bb[2], bb[3]);
            }
        }
        __syncthreads();
    }

    // ---- epilogue 1: store fp16 features ----
#pragma unroll
    for (int ni = 0; ni < 16; ni++) {
        int row0 = block_row + warp_m * 16 + g;
        int col  = warp_n * 128 + ni * 8 + 2 * t;
        if (row0 < N_NODES) {
            *reinterpret_cast<__half2*>(g_fth + (size_t)row0 * FDIM + col) =
                __floats2half2_rn(acc[ni][0], acc[ni][1]);
        }
        int row1 = row0 + 8;
        if (row1 < N_NODES) {
            *reinterpret_cast<__half2*>(g_fth + (size_t)row1 * FDIM + col) =
                __floats2half2_rn(acc[ni][2], acc[ni][3]);
        }
    }

    // ---- epilogue 2: fused a1/a2 (this warp covers heads 2*warp_n, +1) ----
    {
        float p1[2][2], p2[2][2];
#pragma unroll
        for (int hb = 0; hb < 2; hb++)
#pragma unroll
            for (int j = 0; j < 2; j++) { p1[hb][j] = 0.f; p2[hb][j] = 0.f; }

#pragma unroll
        for (int ni = 0; ni < 16; ni++) {
            const int hb = ni >> 3;
            const int h  = warp_n * 2 + hb;
            const int d0 = (ni & 7) * 8 + 2 * t;
            float al0 = attn_l[h * OUT_DIM + d0];
            float al1 = attn_l[h * OUT_DIM + d0 + 1];
            float ar0 = attn_r[h * OUT_DIM + d0];
            float ar1 = attn_r[h * OUT_DIM + d0 + 1];
            p1[hb][0] += acc[ni][0] * al0 + acc[ni][1] * al1;
            p1[hb][1] += acc[ni][2] * al0 + acc[ni][3] * al1;
            p2[hb][0] += acc[ni][0] * ar0 + acc[ni][1] * ar1;
            p2[hb][1] += acc[ni][2] * ar0 + acc[ni][3] * ar1;
        }
#pragma unroll
        for (int hb = 0; hb < 2; hb++)
#pragma unroll
            for (int j = 0; j < 2; j++) {
                p1[hb][j] += __shfl_xor_sync(0xFFFFFFFFu, p1[hb][j], 1);
                p1[hb][j] += __shfl_xor_sync(0xFFFFFFFFu, p1[hb][j], 2);
                p2[hb][j] += __shfl_xor_sync(0xFFFFFFFFu, p2[hb][j], 1);
                p2[hb][j] += __shfl_xor_sync(0xFFFFFFFFu, p2[hb][j], 2);
            }
        if (t == 0) {
            int r0 = block_row + warp_m * 16 + g;
#pragma unroll
            for (int hb = 0; hb < 2; hb++) {
                const int h = warp_n * 2 + hb;
#pragma unroll
                for (int j = 0; j < 2; j++) {
                    int row = r0 + j * 8;
                    if (row < N_NODES) {
                        g_a1[row * HEADS + h] = p1[hb][j];
                        g_a2[row * HEADS + h] = p2[hb][j];
                    }
                }
            }
        }
    }
}

// ---------------- 3) CSR build: vectorized hist, 2-kernel scan, scatter ------
__global__ void hist_kernel(const int* __restrict__ dst) {
    int i4 = (blockIdx.x * blockDim.x + threadIdx.x) * 4;
    if (i4 + 4 <= N_EDGES) {
        int4 d = *reinterpret_cast<const int4*>(dst + i4);
        atomicAdd(&g_deg[d.x], 1);
        atomicAdd(&g_deg[d.y], 1);
        atomicAdd(&g_deg[d.z], 1);
        atomicAdd(&g_deg[d.w], 1);
    } else {
        for (int e = i4; e < N_EDGES; e++) atomicAdd(&g_deg[dst[e]], 1);
    }
}

__global__ __launch_bounds__(SCAN_TPB)
void scan1_kernel() {
    __shared__ int s[SCAN_TPB];
    int tid = threadIdx.x;
    int i = blockIdx.x * SCAN_TPB + tid;
    int v = 0;
    if (i < N_NODES) {
        v = g_deg[i];
        g_deg[i] = 0;              // self-reset for next graph replay
    }
    s[tid] = v;
    __syncthreads();
#pragma unroll
    for (int off = 1; off < SCAN_TPB; off <<= 1) {
        int t = (tid >= off) ? s[tid - off] : 0;
        __syncthreads();
        s[tid] += t;
        __syncthreads();
    }
    if (i < N_NODES) g_rowstart[i] = s[tid] - v;
    if (tid == SCAN_TPB - 1) g_bsum[blockIdx.x] = s[tid];
}

__global__ __launch_bounds__(SCAN_TPB)
void scan23_kernel() {
    __shared__ int s[SCAN_TPB];
    const int tid = threadIdx.x;
    const int bid = blockIdx.x;
    int v = (tid < bid && tid < SCAN_NB) ? g_bsum[tid] : 0;
    s[tid] = v;
    __syncthreads();
#pragma unroll
    for (int off = SCAN_TPB / 2; off > 0; off >>= 1) {
        if (tid < off) s[tid] += s[tid + off];
        __syncthreads();
    }
    const int offset = s[0];
    int i = bid * SCAN_TPB + tid;
    if (i < N_NODES) {
        int r = g_rowstart[i] + offset;
        g_rowstart[i] = r;
        g_cursor[i]   = r;
    }
    if (bid == 0 && tid == 0) g_rowstart[N_NODES] = N_EDGES;
}

__global__ void scatter_kernel(const int* __restrict__ src,
                               const int* __restrict__ dst) {
    int i4 = (blockIdx.x * blockDim.x + threadIdx.x) * 4;
    if (i4 + 4 <= N_EDGES) {
        int4 d = *reinterpret_cast<const int4*>(dst + i4);
        int4 sc = *reinterpret_cast<const int4*>(src + i4);
        g_csr_src[atomicAdd(&g_cursor[d.x], 1)] = sc.x;
        g_csr_src[atomicAdd(&g_cursor[d.y], 1)] = sc.y;
        g_csr_src[atomicAdd(&g_cursor[d.z], 1)] = sc.z;
        g_csr_src[atomicAdd(&g_cursor[d.w], 1)] = sc.w;
    } else {
        for (int e = i4; e < N_EDGES; e++)
            g_csr_src[atomicAdd(&g_cursor[dst[e]], 1)] = src[e];
    }
}

// ---------------- 4) warp-per-node fused GAT aggregation (no segment max) ----
__device__ __forceinline__ float lrelu(float x) {
    return (x > 0.0f) ? x : ALPHA * x;
}
__device__ __forceinline__ float wred_sum(float v) {
#pragma unroll
    for (int o = 16; o > 0; o >>= 1)
        v += __shfl_xor_sync(0xFFFFFFFFu, v, o);
    return v;
}
__device__ __forceinline__ void acc_row(float acc[8], float c, uint4 v) {
    const __half2* hp = reinterpret_cast<const __half2*>(&v);
#pragma unroll
    for (int k = 0; k < 4; k++) {
        float2 f = __half22float2(hp[k]);
        acc[2 * k]     += c * f.x;
        acc[2 * k + 1] += c * f.y;
    }
}

#define GAT_WPB 8   // warps per block

__global__ __launch_bounds__(GAT_WPB * 32)
void gat_warp_kernel(float* __restrict__ out)
{
    const int wid  = threadIdx.x >> 5;
    const int lane = threadIdx.x & 31;
    const int n    = blockIdx.x * GAT_WPB + wid;   // 50000 = 6250*8

    __shared__ float4 s_coef[GAT_WPB][32];
    __shared__ int    s_srcs[GAT_WPB][32];

    const int beg = g_rowstart[n];
    const int end = g_rowstart[n + 1];
    const int deg = end - beg;

    float4 a2v = __ldg(&reinterpret_cast<const float4*>(g_a2)[n]);

    float acc[8];
#pragma unroll
    for (int k = 0; k < 8; k++) acc[k] = 0.0f;
    const int hh = lane >> 3;          // lane owns cols [8*lane, 8*lane+8)

    if (deg <= 32) {
        // ---------- fast path: lane i owns edge i; direct exp, no max ----------
        int   s  = 0;
        float e0 = 0.f, e1 = 0.f, e2 = 0.f, e3 = 0.f;
        if (lane < deg) {
            s = __ldg(&g_csr_src[beg + lane]);
            float4 a1v = __ldg(&reinterpret_cast<const float4*>(g_a1)[s]);
            e0 = __expf(lrelu(a1v.x + a2v.x));
            e1 = __expf(lrelu(a1v.y + a2v.y));
            e2 = __expf(lrelu(a1v.z + a2v.z));
            e3 = __expf(lrelu(a1v.w + a2v.w));
        }
        float i0 = 1.0f / wred_sum(e0), i1 = 1.0f / wred_sum(e1);
        float i2 = 1.0f / wred_sum(e2), i3 = 1.0f / wred_sum(e3);
        if (lane < deg) {
            s_coef[wid][lane] = make_float4(e0 * i0, e1 * i1, e2 * i2, e3 * i3);
            s_srcs[wid][lane] = s;
        }
        __syncwarp();

        const float* cf = reinterpret_cast<const float*>(&s_coef[wid][0]);
        int li = 0;
        for (; li + 8 <= deg; li += 8) {           // 8 loads in flight
            uint4 v[8];
#pragma unroll
            for (int j = 0; j < 8; j++) {
                int sj = s_srcs[wid][li + j];
                v[j] = __ldg(reinterpret_cast<const uint4*>(
                                 g_fth + (size_t)sj * FDIM) + lane);
            }
#pragma unroll
            for (int j = 0; j < 8; j++)
                acc_row(acc, cf[(li + j) * 4 + hh], v[j]);
        }
        for (; li + 4 <= deg; li += 4) {
            uint4 v[4];
#pragma unroll
            for (int j = 0; j < 4; j++) {
                int sj = s_srcs[wid][li + j];
                v[j] = __ldg(reinterpret_cast<const uint4*>(
                                 g_fth + (size_t)sj * FDIM) + lane);
            }
#pragma unroll
            for (int j = 0; j < 4; j++)
                acc_row(acc, cf[(li + j) * 4 + hh], v[j]);
        }
        for (; li < deg; li++) {
            int sa = s_srcs[wid][li];
            uint4 va = __ldg(reinterpret_cast<const uint4*>(
                                 g_fth + (size_t)sa * FDIM) + lane);
            acc_row(acc, cf[li * 4 + hh], va);
        }
    } else {
        // ---------- slow path: strided sum pass + 32-edge coef tiles ----------
        float t0 = 0.f, t1 = 0.f, t2 = 0.f, t3 = 0.f;
        for (int i = beg + lane; i < end; i += 32) {
            int s = g_csr_src[i];
            float4 a1v = __ldg(&reinterpret_cast<const float4*>(g_a1)[s]);
            t0 += __expf(lrelu(a1v.x + a2v.x));
            t1 += __expf(lrelu(a1v.y + a2v.y));
            t2 += __expf(lrelu(a1v.z + a2v.z));
            t3 += __expf(lrelu(a1v.w + a2v.w));
        }
        float i0 = 1.0f / wred_sum(t0), i1 = 1.0f / wred_sum(t1);
        float i2 = 1.0f / wred_sum(t2), i3 = 1.0f / wred_sum(t3);

        const float* cf = reinterpret_cast<const float*>(&s_coef[wid][0]);
        for (int tb = beg; tb < end; tb += 32) {
            int cnt = min(32, end - tb);
            if (lane < cnt) {
                int s = __ldg(&g_csr_src[tb + lane]);
                float4 a1v = __ldg(&reinterpret_cast<const float4*>(g_a1)[s]);
                s_coef[wid][lane] = make_float4(
                    __expf(lrelu(a1v.x + a2v.x)) * i0,
                    __expf(lrelu(a1v.y + a2v.y)) * i1,
                    __expf(lrelu(a1v.z + a2v.z)) * i2,
                    __expf(lrelu(a1v.w + a2v.w)) * i3);
                s_srcs[wid][lane] = s;
            }
            __syncwarp();
            for (int li = 0; li < cnt; li++) {
                int sa = s_srcs[wid][li];
                uint4 va = __ldg(reinterpret_cast<const uint4*>(
                                     g_fth + (size_t)sa * FDIM) + lane);
                acc_row(acc, cf[li * 4 + hh], va);
            }
            __syncwarp();
        }
    }

    // ---- fused ELU + store ----
    float4 o0 = make_float4(
        acc[0] > 0.f ? acc[0] : expm1f(acc[0]),
        acc[1] > 0.f ? acc[1] : expm1f(acc[1]),
        acc[2] > 0.f ? acc[2] : expm1f(acc[2]),
        acc[3] > 0.f ? acc[3] : expm1f(acc[3]));
    float4 o1 = make_float4(
        acc[4] > 0.f ? acc[4] : expm1f(acc[4]),
        acc[5] > 0.f ? acc[5] : expm1f(acc[5]),
        acc[6] > 0.f ? acc[6] : expm1f(acc[6]),
        acc[7] > 0.f ? acc[7] : expm1f(acc[7]));
    float4* op = reinterpret_cast<float4*>(out + (size_t)n * FDIM + 8 * lane);
    op[0] = o0;
    op[1] = o1;
}

// ---------------- launch ------------------------------------------------------
extern "C" void kernel_launch(void* const* d_in, const int* in_sizes, int n_in,
                              void* d_out, int out_size)
{
    const float* feat   = (const float*)d_in[0];
    const int*   src    = (const int*)  d_in[1];
    const int*   dst    = (const int*)  d_in[2];
    const float* W      = (const float*)d_in[3];
    const float* attn_l = (const float*)d_in[4];
    const float* attn_r = (const float*)d_in[5];
    float* out = (float*)d_out;

    const int TPB = 256;
    const int E4  = (N_EDGES / 4 + TPB - 1) / TPB;

    static cudaStream_t s_side = nullptr;
    static cudaEvent_t  ev_fork = nullptr, ev_join = nullptr;
    if (s_side == nullptr) {
        cudaStreamCreateWithFlags(&s_side, cudaStreamNonBlocking);
        cudaEventCreateWithFlags(&ev_fork, cudaEventDisableTiming);
        cudaEventCreateWithFlags(&ev_join, cudaEventDisableTiming);
    }

    // ---- fork: side stream runs wconv+GEMM(+a1a2); main runs CSR build ----
    cudaEventRecord(ev_fork, 0);
    cudaStreamWaitEvent(s_side, ev_fork, 0);

    {
        wconv_kernel<<<(FDIM * IN_DIM / 4 + TPB - 1) / TPB, TPB, 0, s_side>>>(W);
        dim3 grid((N_NODES + GBM - 1) / GBM, 1);
        gemm_f16x2_kernel<<<grid, 256, 0, s_side>>>(feat, attn_l, attn_r);
    }

    hist_kernel<<<E4, TPB>>>(dst);
    scan1_kernel<<<SCAN_NB, SCAN_TPB>>>();
    scan23_kernel<<<SCAN_NB, SCAN_TPB>>>();
    scatter_kernel<<<E4, TPB>>>(src, dst);

    // ---- join ----
    cudaEventRecord(ev_join, s_side);
    cudaStreamWaitEvent(0, ev_join, 0);

    gat_warp_kernel<<<N_NODES / GAT_WPB, GAT_WPB * 32>>>(out);
}

// round 16
// speedup vs baseline: 1.0661x; 1.0661x over previous
#include <cuda_runtime.h>
#include <cuda_fp16.h>
#include <cstdint>
#include <cfloat>

#define N_NODES 50000
#define N_EDGES 800000
#define IN_DIM  256
#define HEADS   4
#define OUT_DIM 64
#define FDIM    256            // HEADS * OUT_DIM
#define ALPHA   0.2f

#define SCAN_TPB 256
#define SCAN_NB  ((N_NODES + SCAN_TPB - 1) / SCAN_TPB)   // 196

// ---------------- scratch (static device globals; no allocation) -------------
__device__ __half g_fth[N_NODES * FDIM];     // projected features, fp16 [N,256]
__device__ __half g_Wh [FDIM * IN_DIM];      // W pre-converted to fp16 [256,256]
__device__ float  g_a1 [N_NODES * HEADS];    // src-side attn term [N,4]
__device__ float  g_a2 [N_NODES * HEADS];    // dst-side attn term [N,4]
__device__ int    g_deg     [N_NODES];       // in-degree histogram (self-resetting)
__device__ int    g_rowstart[N_NODES + 1];   // CSR row offsets (by dst)
__device__ int    g_cursor  [N_NODES];       // scatter cursors
__device__ int    g_csr_src [N_EDGES];       // CSR payload: src node per slot
__device__ int    g_bsum [SCAN_NB];          // scan block sums

// ---------------- 0) W -> fp16 conversion (once per launch, deterministic) ---
__global__ void wconv_kernel(const float* __restrict__ Wm) {
    int i = (blockIdx.x * blockDim.x + threadIdx.x) * 4;
    if (i < FDIM * IN_DIM) {
        float4 v = *reinterpret_cast<const float4*>(Wm + i);
        __half2 a = __floats2half2_rn(v.x, v.y);
        __half2 b = __floats2half2_rn(v.z, v.w);
        *reinterpret_cast<uint2*>(g_Wh + i) =
            make_uint2(reinterpret_cast<uint32_t&>(a),
                       reinterpret_cast<uint32_t&>(b));
    }
}

// ---------------- 1) GEMM (fp16 split-A, GBM=128 full-width N) + a1a2 --------
#define GBM 128
#define GBN 256
#define GBK 32
#define LDT 40   // padded fp16 row stride: 80B rows, 16B-aligned 8x8 tiles

__device__ __forceinline__ void split2h(float a, float b,
                                        uint32_t& hi, uint32_t& lo) {
    __half2 hp = __floats2half2_rn(a, b);
    hi = reinterpret_cast<uint32_t&>(hp);
    __half2 lp = __floats2half2_rn(a - __half2float(__low2half(hp)),
                                   b - __half2float(__high2half(hp)));
    lo = reinterpret_cast<uint32_t&>(lp);
}

__device__ __forceinline__ void mma_f16(float c[4],
                                        const uint32_t a[4],
                                        const uint32_t b0, const uint32_t b1) {
    asm volatile(
        "mma.sync.aligned.m16n8k16.row.col.f32.f16.f16.f32 "
        "{%0,%1,%2,%3}, {%4,%5,%6,%7}, {%8,%9}, {%0,%1,%2,%3};\n"
        : "+f"(c[0]), "+f"(c[1]), "+f"(c[2]), "+f"(c[3])
        : "r"(a[0]), "r"(a[1]), "r"(a[2]), "r"(a[3]), "r"(b0), "r"(b1));
}

__device__ __forceinline__ void ldsm_x4(uint32_t r[4], uint32_t addr) {
    asm volatile(
        "ldmatrix.sync.aligned.m8n8.x4.shared.b16 {%0,%1,%2,%3}, [%4];"
        : "=r"(r[0]), "=r"(r[1]), "=r"(r[2]), "=r"(r[3]) : "r"(addr));
}

__global__ __launch_bounds__(256)
void gemm_f16x2_kernel(const float* __restrict__ A,
                       const float* __restrict__ attn_l,
                       const float* __restrict__ attn_r)
{
    __shared__ __half Ah[GBM * LDT], Al[GBM * LDT];
    __shared__ __half Bh[GBN * LDT];

    const int tid  = threadIdx.x;
    const int warp = tid >> 5, lane = tid & 31;
    const int g = lane >> 2, t = lane & 3;
    const int warp_m = warp >> 1;          // 0..3 (32 M-rows each)
    const int warp_n = warp & 1;           // 0..1 (128 N-cols each)
    const int block_row = blockIdx.x * GBM;

    float acc[2][16][4];
#pragma unroll
    for (int mi = 0; mi < 2; mi++)
#pragma unroll
        for (int ni = 0; ni < 16; ni++)
#pragma unroll
            for (int i = 0; i < 4; i++) acc[mi][ni][i] = 0.0f;

    const int lrow = tid >> 1;             // A row 0..127
    const int lk0  = (tid & 1) * 16;       // A k-slice 0 or 16
    const int ar   = block_row + lrow;
    const bool aok = (ar < N_NODES);
    const int br   = tid;                  // B row 0..255 (full W)

    const uint32_t ah_base = (uint32_t)__cvta_generic_to_shared(Ah);
    const uint32_t al_base = (uint32_t)__cvta_generic_to_shared(Al);
    const uint32_t bh_base = (uint32_t)__cvta_generic_to_shared(Bh);
    const uint32_t a_off = 2u * ((uint32_t)(warp_m * 32 + (lane & 15)) * LDT
                                 + (uint32_t)((lane >> 4) * 8));
    const uint32_t b_off = 2u * ((uint32_t)(warp_n * 128 + ((lane >> 4) << 3)
                                            + (lane & 7)) * LDT
                                 + (uint32_t)(((lane >> 3) & 1) << 3));

    float4 pa[4];
    uint4  pbv[4];
#pragma unroll
    for (int q = 0; q < 4; q++) {
        int ko = lk0 + q * 4;
        pa[q] = aok ? *reinterpret_cast<const float4*>(A + (size_t)ar * IN_DIM + ko)
                    : make_float4(0.f, 0.f, 0.f, 0.f);
    }
#pragma unroll
    for (int q = 0; q < 4; q++) {
        pbv[q] = *reinterpret_cast<const uint4*>(g_Wh + (size_t)br * IN_DIM + q * 8);
    }

    for (int k0 = 0; k0 < IN_DIM; k0 += GBK) {
        // ---- split A + copy pre-converted B into smem ----
#pragma unroll
        for (int q = 0; q < 4; q++) {
            int ko = lk0 + q * 4;
            uint32_t h01, l01, h23, l23;
            split2h(pa[q].x, pa[q].y, h01, l01);
            split2h(pa[q].z, pa[q].w, h23, l23);
            *reinterpret_cast<uint2*>(&Ah[lrow * LDT + ko]) = make_uint2(h01, h23);
            *reinterpret_cast<uint2*>(&Al[lrow * LDT + ko]) = make_uint2(l01, l23);
        }
#pragma unroll
        for (int q = 0; q < 4; q++) {
            *reinterpret_cast<uint4*>(&Bh[br * LDT + q * 8]) = pbv[q];
        }
        __syncthreads();

        // ---- prefetch next tile ----
        int kn = k0 + GBK;
        if (kn < IN_DIM) {
#pragma unroll
            for (int q = 0; q < 4; q++) {
                int ko = kn + lk0 + q * 4;
                pa[q] = aok ? *reinterpret_cast<const float4*>(
                                  A + (size_t)ar * IN_DIM + ko)
                            : make_float4(0.f, 0.f, 0.f, 0.f);
            }
#pragma unroll
            for (int q = 0; q < 4; q++) {
                pbv[q] = *reinterpret_cast<const uint4*>(
                             g_Wh + (size_t)br * IN_DIM + kn + q * 8);
            }
        }

        // ---- MMA compute (ldmatrix fragments) ----
#pragma unroll
        for (int kk = 0; kk < GBK; kk += 16) {
            uint32_t ah[2][4], al[2][4];
            ldsm_x4(ah[0], ah_base + a_off + 2 * kk);
            ldsm_x4(ah[1], ah_base + a_off + 2 * (16 * LDT + kk));
            ldsm_x4(al[0], al_base + a_off + 2 * kk);
            ldsm_x4(al[1], al_base + a_off + 2 * (16 * LDT + kk));
#pragma unroll
            for (int p = 0; p < 8; p++) {        // 16 ni as 8 pairs
                uint32_t bb[4];
                ldsm_x4(bb, bh_base + b_off + 2 * (p * 16 * LDT + kk));
#pragma unroll
                for (int mi = 0; mi < 2; mi++) {
                    mma_f16(acc[mi][2 * p],     ah[mi], bb[0], bb[1]);
                    mma_f16(acc[mi][2 * p],     al[mi], bb[0], bb[1]);
                    mma_f16(acc[mi][2 * p + 1], ah[mi], bb[2], bb[3]);
                    mma_f16(acc[mi][2 * p + 1], al[mi], bb[2], bb[3]);
                }
            }
        }
        __syncthreads();
    }

    // ---- epilogue 1: store fp16 features ----
#pragma unroll
    for (int mi = 0; mi < 2; mi++) {
#pragma unroll
        for (int ni = 0; ni < 16; ni++) {
            int row0 = block_row + warp_m * 32 + mi * 16 + g;
            int col  = warp_n * 128 + ni * 8 + 2 * t;
            if (row0 < N_NODES) {
                *reinterpret_cast<__half2*>(g_fth + (size_t)row0 * FDIM + col) =
                    __floats2half2_rn(acc[mi][ni][0], acc[mi][ni][1]);
            }
            int row1 = row0 + 8;
            if (row1 < N_NODES) {
                *reinterpret_cast<__half2*>(g_fth + (size_t)row1 * FDIM + col) =
                    __floats2half2_rn(acc[mi][ni][2], acc[mi][ni][3]);
            }
        }
    }

    // ---- epilogue 2: fused a1/a2 (this warp covers heads 2*warp_n, 2*warp_n+1)
    {
        float p1[2][4], p2[2][4];
#pragma unroll
        for (int hb = 0; hb < 2; hb++)
#pragma unroll
            for (int j = 0; j < 4; j++) { p1[hb][j] = 0.f; p2[hb][j] = 0.f; }

#pragma unroll
        for (int ni = 0; ni < 16; ni++) {
            const int hb = ni >> 3;                 // which of this warp's 2 heads
            const int h  = warp_n * 2 + hb;
            const int d0 = (ni & 7) * 8 + 2 * t;
            float al0 = attn_l[h * OUT_DIM + d0];
            float al1 = attn_l[h * OUT_DIM + d0 + 1];
            float ar0 = attn_r[h * OUT_DIM + d0];
            float ar1 = attn_r[h * OUT_DIM + d0 + 1];
#pragma unroll
            for (int mi = 0; mi < 2; mi++) {
                p1[hb][mi * 2 + 0] += acc[mi][ni][0] * al0 + acc[mi][ni][1] * al1;
                p1[hb][mi * 2 + 1] += acc[mi][ni][2] * al0 + acc[mi][ni][3] * al1;
                p2[hb][mi * 2 + 0] += acc[mi][ni][0] * ar0 + acc[mi][ni][1] * ar1;
                p2[hb][mi * 2 + 1] += acc[mi][ni][2] * ar0 + acc[mi][ni][3] * ar1;
            }
        }
#pragma unroll
        for (int hb = 0; hb < 2; hb++)
#pragma unroll
            for (int j = 0; j < 4; j++) {
                p1[hb][j] += __shfl_xor_sync(0xFFFFFFFFu, p1[hb][j], 1);
                p1[hb][j] += __shfl_xor_sync(0xFFFFFFFFu, p1[hb][j], 2);
                p2[hb][j] += __shfl_xor_sync(0xFFFFFFFFu, p2[hb][j], 1);
                p2[hb][j] += __shfl_xor_sync(0xFFFFFFFFu, p2[hb][j], 2);
            }
        if (t == 0) {
            int r0 = block_row + warp_m * 32 + g;
#pragma unroll
            for (int hb = 0; hb < 2; hb++) {
                const int h = warp_n * 2 + hb;
#pragma unroll
                for (int j = 0; j < 4; j++) {
                    int row = r0 + (j >> 1) * 16 + (j & 1) * 8;
                    if (row < N_NODES) {
                        g_a1[row * HEADS + h] = p1[hb][j];
                        g_a2[row * HEADS + h] = p2[hb][j];
                    }
                }
            }
        }
    }
}

// ---------------- 3) CSR build: vectorized hist, 2-kernel scan, scatter ------
__global__ void hist_kernel(const int* __restrict__ dst) {
    int i4 = (blockIdx.x * blockDim.x + threadIdx.x) * 4;
    if (i4 + 4 <= N_EDGES) {
        int4 d = *reinterpret_cast<const int4*>(dst + i4);
        atomicAdd(&g_deg[d.x], 1);
        atomicAdd(&g_deg[d.y], 1);
        atomicAdd(&g_deg[d.z], 1);
        atomicAdd(&g_deg[d.w], 1);
    } else {
        for (int e = i4; e < N_EDGES; e++) atomicAdd(&g_deg[dst[e]], 1);
    }
}

__global__ __launch_bounds__(SCAN_TPB)
void scan1_kernel() {
    __shared__ int s[SCAN_TPB];
    int tid = threadIdx.x;
    int i = blockIdx.x * SCAN_TPB + tid;
    int v = 0;
    if (i < N_NODES) {
        v = g_deg[i];
        g_deg[i] = 0;              // self-reset for next graph replay
    }
    s[tid] = v;
    __syncthreads();
#pragma unroll
    for (int off = 1; off < SCAN_TPB; off <<= 1) {
        int t = (tid >= off) ? s[tid - off] : 0;
        __syncthreads();
        s[tid] += t;
        __syncthreads();
    }
    if (i < N_NODES) g_rowstart[i] = s[tid] - v;
    if (tid == SCAN_TPB - 1) g_bsum[blockIdx.x] = s[tid];
}

__global__ __launch_bounds__(SCAN_TPB)
void scan23_kernel() {
    __shared__ int s[SCAN_TPB];
    const int tid = threadIdx.x;
    const int bid = blockIdx.x;
    int v = (tid < bid && tid < SCAN_NB) ? g_bsum[tid] : 0;
    s[tid] = v;
    __syncthreads();
#pragma unroll
    for (int off = SCAN_TPB / 2; off > 0; off >>= 1) {
        if (tid < off) s[tid] += s[tid + off];
        __syncthreads();
    }
    const int offset = s[0];
    int i = bid * SCAN_TPB + tid;
    if (i < N_NODES) {
        int r = g_rowstart[i] + offset;
        g_rowstart[i] = r;
        g_cursor[i]   = r;
    }
    if (bid == 0 && tid == 0) g_rowstart[N_NODES] = N_EDGES;
}

__global__ void scatter_kernel(const int* __restrict__ src,
                               const int* __restrict__ dst) {
    int i4 = (blockIdx.x * blockDim.x + threadIdx.x) * 4;
    if (i4 + 4 <= N_EDGES) {
        int4 d = *reinterpret_cast<const int4*>(dst + i4);
        int4 sc = *reinterpret_cast<const int4*>(src + i4);
        g_csr_src[atomicAdd(&g_cursor[d.x], 1)] = sc.x;
        g_csr_src[atomicAdd(&g_cursor[d.y], 1)] = sc.y;
        g_csr_src[atomicAdd(&g_cursor[d.z], 1)] = sc.z;
        g_csr_src[atomicAdd(&g_cursor[d.w], 1)] = sc.w;
    } else {
        for (int e = i4; e < N_EDGES; e++)
            g_csr_src[atomicAdd(&g_cursor[dst[e]], 1)] = src[e];
    }
}

// ---------------- 4) warp-per-node fused GAT aggregation (no segment max) ----
__device__ __forceinline__ float lrelu(float x) {
    return (x > 0.0f) ? x : ALPHA * x;
}
__device__ __forceinline__ float wred_sum(float v) {
#pragma unroll
    for (int o = 16; o > 0; o >>= 1)
        v += __shfl_xor_sync(0xFFFFFFFFu, v, o);
    return v;
}
__device__ __forceinline__ void acc_row(float acc[8], float c, uint4 v) {
    const __half2* hp = reinterpret_cast<const __half2*>(&v);
#pragma unroll
    for (int k = 0; k < 4; k++) {
        float2 f = __half22float2(hp[k]);
        acc[2 * k]     += c * f.x;
        acc[2 * k + 1] += c * f.y;
    }
}

#define GAT_WPB 8   // warps per block

__global__ __launch_bounds__(GAT_WPB * 32)
void gat_warp_kernel(float* __restrict__ out)
{
    const int wid  = threadIdx.x >> 5;
    const int lane = threadIdx.x & 31;
    const int n    = blockIdx.x * GAT_WPB + wid;   // 50000 = 6250*8

    __shared__ float4 s_coef[GAT_WPB][32];
    __shared__ int    s_srcs[GAT_WPB][32];

    const int beg = g_rowstart[n];
    const int end = g_rowstart[n + 1];
    const int deg = end - beg;

    float4 a2v = __ldg(&reinterpret_cast<const float4*>(g_a2)[n]);

    float acc[8];
#pragma unroll
    for (int k = 0; k < 8; k++) acc[k] = 0.0f;
    const int hh = lane >> 3;          // lane owns cols [8*lane, 8*lane+8)

    if (deg <= 32) {
        // ---------- fast path: lane i owns edge i; direct exp, no max ----------
        int   s  = 0;
        float e0 = 0.f, e1 = 0.f, e2 = 0.f, e3 = 0.f;
        if (lane < deg) {
            s = __ldg(&g_csr_src[beg + lane]);
            float4 a1v = __ldg(&reinterpret_cast<const float4*>(g_a1)[s]);
            e0 = __expf(lrelu(a1v.x + a2v.x));
            e1 = __expf(lrelu(a1v.y + a2v.y));
            e2 = __expf(lrelu(a1v.z + a2v.z));
            e3 = __expf(lrelu(a1v.w + a2v.w));
        }
        float i0 = 1.0f / wred_sum(e0), i1 = 1.0f / wred_sum(e1);
        float i2 = 1.0f / wred_sum(e2), i3 = 1.0f / wred_sum(e3);
        if (lane < deg) {
            s_coef[wid][lane] = make_float4(e0 * i0, e1 * i1, e2 * i2, e3 * i3);
            s_srcs[wid][lane] = s;
        }
        __syncwarp();

        const float* cf = reinterpret_cast<const float*>(&s_coef[wid][0]);
        int li = 0;
        for (; li + 8 <= deg; li += 8) {           // 8 loads in flight
            uint4 v[8];
#pragma unroll
            for (int j = 0; j < 8; j++) {
                int sj = s_srcs[wid][li + j];
                v[j] = __ldg(reinterpret_cast<const uint4*>(
                                 g_fth + (size_t)sj * FDIM) + lane);
            }
#pragma unroll
            for (int j = 0; j < 8; j++)
                acc_row(acc, cf[(li + j) * 4 + hh], v[j]);
        }
        for (; li + 4 <= deg; li += 4) {
            uint4 v[4];
#pragma unroll
            for (int j = 0; j < 4; j++) {
                int sj = s_srcs[wid][li + j];
                v[j] = __ldg(reinterpret_cast<const uint4*>(
                                 g_fth + (size_t)sj * FDIM) + lane);
            }
#pragma unroll
            for (int j = 0; j < 4; j++)
                acc_row(acc, cf[(li + j) * 4 + hh], v[j]);
        }
        for (; li < deg; li++) {
            int sa = s_srcs[wid][li];
            uint4 va = __ldg(reinterpret_cast<const uint4*>(
                                 g_fth + (size_t)sa * FDIM) + lane);
            acc_row(acc, cf[li * 4 + hh], va);
        }
    } else {
        // ---------- slow path: strided sum pass + 32-edge coef tiles ----------
        float t0 = 0.f, t1 = 0.f, t2 = 0.f, t3 = 0.f;
        for (int i = beg + lane; i < end; i += 32) {
            int s = g_csr_src[i];
            float4 a1v = __ldg(&reinterpret_cast<const float4*>(g_a1)[s]);
            t0 += __expf(lrelu(a1v.x + a2v.x));
            t1 += __expf(lrelu(a1v.y + a2v.y));
            t2 += __expf(lrelu(a1v.z + a2v.z));
            t3 += __expf(lrelu(a1v.w + a2v.w));
        }
        float i0 = 1.0f / wred_sum(t0), i1 = 1.0f / wred_sum(t1);
        float i2 = 1.0f / wred_sum(t2), i3 = 1.0f / wred_sum(t3);

        const float* cf = reinterpret_cast<const float*>(&s_coef[wid][0]);
        for (int tb = beg; tb < end; tb += 32) {
            int cnt = min(32, end - tb);
            if (lane < cnt) {
                int s = __ldg(&g_csr_src[tb + lane]);
                float4 a1v = __ldg(&reinterpret_cast<const float4*>(g_a1)[s]);
                s_coef[wid][lane] = make_float4(
                    __expf(lrelu(a1v.x + a2v.x)) * i0,
                    __expf(lrelu(a1v.y + a2v.y)) * i1,
                    __expf(lrelu(a1v.z + a2v.z)) * i2,
                    __expf(lrelu(a1v.w + a2v.w)) * i3);
                s_srcs[wid][lane] = s;
            }
            __syncwarp();
            for (int li = 0; li < cnt; li++) {
                int sa = s_srcs[wid][li];
                uint4 va = __ldg(reinterpret_cast<const uint4*>(
                                     g_fth + (size_t)sa * FDIM) + lane);
                acc_row(acc, cf[li * 4 + hh], va);
            }
            __syncwarp();
        }
    }

    // ---- fused ELU + store ----
    float4 o0 = make_float4(
        acc[0] > 0.f ? acc[0] : expm1f(acc[0]),
        acc[1] > 0.f ? acc[1] : expm1f(acc[1]),
        acc[2] > 0.f ? acc[2] : expm1f(acc[2]),
        acc[3] > 0.f ? acc[3] : expm1f(acc[3]));
    float4 o1 = make_float4(
        acc[4] > 0.f ? acc[4] : expm1f(acc[4]),
        acc[5] > 0.f ? acc[5] : expm1f(acc[5]),
        acc[6] > 0.f ? acc[6] : expm1f(acc[6]),
        acc[7] > 0.f ? acc[7] : expm1f(acc[7]));
    float4* op = reinterpret_cast<float4*>(out + (size_t)n * FDIM + 8 * lane);
    op[0] = o0;
    op[1] = o1;
}

// ---------------- launch ------------------------------------------------------
extern "C" void kernel_launch(void* const* d_in, const int* in_sizes, int n_in,
                              void* d_out, int out_size)
{
    const float* feat   = (const float*)d_in[0];
    const int*   src    = (const int*)  d_in[1];
    const int*   dst    = (const int*)  d_in[2];
    const float* W      = (const float*)d_in[3];
    const float* attn_l = (const float*)d_in[4];
    const float* attn_r = (const float*)d_in[5];
    float* out = (float*)d_out;

    const int TPB = 256;
    const int E4  = (N_EDGES / 4 + TPB - 1) / TPB;

    static cudaStream_t s_side = nullptr;
    static cudaEvent_t  ev_fork = nullptr, ev_join = nullptr;
    if (s_side == nullptr) {
        cudaStreamCreateWithFlags(&s_side, cudaStreamNonBlocking);
        cudaEventCreateWithFlags(&ev_fork, cudaEventDisableTiming);
        cudaEventCreateWithFlags(&ev_join, cudaEventDisableTiming);
    }

    // ---- fork: side stream runs wconv+GEMM(+a1a2); main runs CSR build ----
    cudaEventRecord(ev_fork, 0);
    cudaStreamWaitEvent(s_side, ev_fork, 0);

    {
        wconv_kernel<<<(FDIM * IN_DIM / 4 + TPB - 1) / TPB, TPB, 0, s_side>>>(W);
        dim3 grid((N_NODES + GBM - 1) / GBM, 1);
        gemm_f16x2_kernel<<<grid, 256, 0, s_side>>>(feat, attn_l, attn_r);
    }

    hist_kernel<<<E4, TPB>>>(dst);
    scan1_kernel<<<SCAN_NB, SCAN_TPB>>>();
    scan23_kernel<<<SCAN_NB, SCAN_TPB>>>();
    scatter_kernel<<<E4, TPB>>>(src, dst);

    // ---- join ----
    cudaEventRecord(ev_join, s_side);
    cudaStreamWaitEvent(0, ev_join, 0);

    gat_warp_kernel<<<N_NODES / GAT_WPB, GAT_WPB * 32>>>(out);
}

// round 17
// speedup vs baseline: 1.1167x; 1.0474x over previous
#include <cuda_runtime.h>
#include <cuda_fp16.h>
#include <cstdint>
#include <cfloat>

#define N_NODES 50000
#define N_EDGES 800000
#define IN_DIM  256
#define HEADS   4
#define OUT_DIM 64
#define FDIM    256            // HEADS * OUT_DIM
#define ALPHA   0.2f

#define SCAN_TPB 256
#define SCAN_NB  ((N_NODES + SCAN_TPB - 1) / SCAN_TPB)   // 196

// ---------------- scratch (static device globals; no allocation) -------------
__device__ __half g_fth[N_NODES * FDIM];     // projected features, fp16 [N,256]
__device__ __half g_Wh [FDIM * IN_DIM];      // W pre-converted to fp16 [256,256]
__device__ float  g_a1 [N_NODES * HEADS];    // src-side attn term [N,4]
__device__ float  g_a2 [N_NODES * HEADS];    // dst-side attn term [N,4]
__device__ int    g_deg     [N_NODES];       // in-degree histogram (self-resetting)
__device__ int    g_rowstart[N_NODES + 1];   // CSR row offsets (by dst)
__device__ int    g_cursor  [N_NODES];       // scatter cursors
__device__ int    g_csr_src [N_EDGES];       // CSR payload: src node per slot
__device__ int    g_bsum [SCAN_NB];          // scan block sums

// ---------------- 0) W -> fp16 conversion (once per launch, deterministic) ---
__global__ void wconv_kernel(const float* __restrict__ Wm) {
    int i = (blockIdx.x * blockDim.x + threadIdx.x) * 4;
    if (i < FDIM * IN_DIM) {
        float4 v = *reinterpret_cast<const float4*>(Wm + i);
        __half2 a = __floats2half2_rn(v.x, v.y);
        __half2 b = __floats2half2_rn(v.z, v.w);
        *reinterpret_cast<uint2*>(g_Wh + i) =
            make_uint2(reinterpret_cast<uint32_t&>(a),
                       reinterpret_cast<uint32_t&>(b));
    }
}

// ---------------- 1) GEMM (single fp16 A x fp16 B, GBM=128) + a1a2 -----------
#define GBM 128
#define GBN 256
#define GBK 32
#define LDT 40   // padded fp16 row stride: 80B rows, 16B-aligned 8x8 tiles

__device__ __forceinline__ uint32_t pack_h2(float a, float b) {
    __half2 hp = __floats2half2_rn(a, b);
    return reinterpret_cast<uint32_t&>(hp);
}

__device__ __forceinline__ void mma_f16(float c[4],
                                        const uint32_t a[4],
                                        const uint32_t b0, const uint32_t b1) {
    asm volatile(
        "mma.sync.aligned.m16n8k16.row.col.f32.f16.f16.f32 "
        "{%0,%1,%2,%3}, {%4,%5,%6,%7}, {%8,%9}, {%0,%1,%2,%3};\n"
        : "+f"(c[0]), "+f"(c[1]), "+f"(c[2]), "+f"(c[3])
        : "r"(a[0]), "r"(a[1]), "r"(a[2]), "r"(a[3]), "r"(b0), "r"(b1));
}

__device__ __forceinline__ void ldsm_x4(uint32_t r[4], uint32_t addr) {
    asm volatile(
        "ldmatrix.sync.aligned.m8n8.x4.shared.b16 {%0,%1,%2,%3}, [%4];"
        : "=r"(r[0]), "=r"(r[1]), "=r"(r[2]), "=r"(r[3]) : "r"(addr));
}

__global__ __launch_bounds__(256)
void gemm_f16x2_kernel(const float* __restrict__ A,
                       const float* __restrict__ attn_l,
                       const float* __restrict__ attn_r)
{
    __shared__ __half Ah[GBM * LDT];
    __shared__ __half Bh[GBN * LDT];

    const int tid  = threadIdx.x;
    const int warp = tid >> 5, lane = tid & 31;
    const int g = lane >> 2, t = lane & 3;
    const int warp_m = warp >> 1;          // 0..3 (32 M-rows each)
    const int warp_n = warp & 1;           // 0..1 (128 N-cols each)
    const int block_row = blockIdx.x * GBM;

    float acc[2][16][4];
#pragma unroll
    for (int mi = 0; mi < 2; mi++)
#pragma unroll
        for (int ni = 0; ni < 16; ni++)
#pragma unroll
            for (int i = 0; i < 4; i++) acc[mi][ni][i] = 0.0f;

    const int lrow = tid >> 1;             // A row 0..127
    const int lk0  = (tid & 1) * 16;       // A k-slice 0 or 16
    const int ar   = block_row + lrow;
    const bool aok = (ar < N_NODES);
    const int br   = tid;                  // B row 0..255 (full W)

    const uint32_t ah_base = (uint32_t)__cvta_generic_to_shared(Ah);
    const uint32_t bh_base = (uint32_t)__cvta_generic_to_shared(Bh);
    const uint32_t a_off = 2u * ((uint32_t)(warp_m * 32 + (lane & 15)) * LDT
                                 + (uint32_t)((lane >> 4) * 8));
    const uint32_t b_off = 2u * ((uint32_t)(warp_n * 128 + ((lane >> 4) << 3)
                                            + (lane & 7)) * LDT
                                 + (uint32_t)(((lane >> 3) & 1) << 3));

    float4 pa[4];
    uint4  pbv[4];
#pragma unroll
    for (int q = 0; q < 4; q++) {
        int ko = lk0 + q * 4;
        pa[q] = aok ? *reinterpret_cast<const float4*>(A + (size_t)ar * IN_DIM + ko)
                    : make_float4(0.f, 0.f, 0.f, 0.f);
    }
#pragma unroll
    for (int q = 0; q < 4; q++) {
        pbv[q] = *reinterpret_cast<const uint4*>(g_Wh + (size_t)br * IN_DIM + q * 8);
    }

    for (int k0 = 0; k0 < IN_DIM; k0 += GBK) {
        // ---- pack A to fp16 + copy pre-converted B into smem ----
#pragma unroll
        for (int q = 0; q < 4; q++) {
            int ko = lk0 + q * 4;
            *reinterpret_cast<uint2*>(&Ah[lrow * LDT + ko]) =
                make_uint2(pack_h2(pa[q].x, pa[q].y), pack_h2(pa[q].z, pa[q].w));
        }
#pragma unroll
        for (int q = 0; q < 4; q++) {
            *reinterpret_cast<uint4*>(&Bh[br * LDT + q * 8]) = pbv[q];
        }
        __syncthreads();

        // ---- prefetch next tile ----
        int kn = k0 + GBK;
        if (kn < IN_DIM) {
#pragma unroll
            for (int q = 0; q < 4; q++) {
                int ko = kn + lk0 + q * 4;
                pa[q] = aok ? *reinterpret_cast<const float4*>(
                                  A + (size_t)ar * IN_DIM + ko)
                            : make_float4(0.f, 0.f, 0.f, 0.f);
            }
#pragma unroll
            for (int q = 0; q < 4; q++) {
                pbv[q] = *reinterpret_cast<const uint4*>(
                             g_Wh + (size_t)br * IN_DIM + kn + q * 8);
            }
        }

        // ---- MMA compute (ldmatrix fragments) ----
#pragma unroll
        for (int kk = 0; kk < GBK; kk += 16) {
            uint32_t ah[2][4];
            ldsm_x4(ah[0], ah_base + a_off + 2 * kk);
            ldsm_x4(ah[1], ah_base + a_off + 2 * (16 * LDT + kk));
#pragma unroll
            for (int p = 0; p < 8; p++) {        // 16 ni as 8 pairs
                uint32_t bb[4];
                ldsm_x4(bb, bh_base + b_off + 2 * (p * 16 * LDT + kk));
#pragma unroll
                for (int mi = 0; mi < 2; mi++) {
                    mma_f16(acc[mi][2 * p],     ah[mi], bb[0], bb[1]);
                    mma_f16(acc[mi][2 * p + 1], ah[mi], bb[2], bb[3]);
                }
            }
        }
        __syncthreads();
    }

    // ---- epilogue 1: store fp16 features ----
#pragma unroll
    for (int mi = 0; mi < 2; mi++) {
#pragma unroll
        for (int ni = 0; ni < 16; ni++) {
            int row0 = block_row + warp_m * 32 + mi * 16 + g;
            int col  = warp_n * 128 + ni * 8 + 2 * t;
            if (row0 < N_NODES) {
                *reinterpret_cast<__half2*>(g_fth + (size_t)row0 * FDIM + col) =
                    __floats2half2_rn(acc[mi][ni][0], acc[mi][ni][1]);
            }
            int row1 = row0 + 8;
            if (row1 < N_NODES) {
                *reinterpret_cast<__half2*>(g_fth + (size_t)row1 * FDIM + col) =
                    __floats2half2_rn(acc[mi][ni][2], acc[mi][ni][3]);
            }
        }
    }

    // ---- epilogue 2: fused a1/a2 (this warp covers heads 2*warp_n, 2*warp_n+1)
    {
        float p1[2][4], p2[2][4];
#pragma unroll
        for (int hb = 0; hb < 2; hb++)
#pragma unroll
            for (int j = 0; j < 4; j++) { p1[hb][j] = 0.f; p2[hb][j] = 0.f; }

#pragma unroll
        for (int ni = 0; ni < 16; ni++) {
            const int hb = ni >> 3;                 // which of this warp's 2 heads
            const int h  = warp_n * 2 + hb;
            const int d0 = (ni & 7) * 8 + 2 * t;
            float al0 = attn_l[h * OUT_DIM + d0];
            float al1 = attn_l[h * OUT_DIM + d0 + 1];
            float ar0 = attn_r[h * OUT_DIM + d0];
            float ar1 = attn_r[h * OUT_DIM + d0 + 1];
#pragma unroll
            for (int mi = 0; mi < 2; mi++) {
                p1[hb][mi * 2 + 0] += acc[mi][ni][0] * al0 + acc[mi][ni][1] * al1;
                p1[hb][mi * 2 + 1] += acc[mi][ni][2] * al0 + acc[mi][ni][3] * al1;
                p2[hb][mi * 2 + 0] += acc[mi][ni][0] * ar0 + acc[mi][ni][1] * ar1;
                p2[hb][mi * 2 + 1] += acc[mi][ni][2] * ar0 + acc[mi][ni][3] * ar1;
            }
        }
#pragma unroll
        for (int hb = 0; hb < 2; hb++)
#pragma unroll
            for (int j = 0; j < 4; j++) {
                p1[hb][j] += __shfl_xor_sync(0xFFFFFFFFu, p1[hb][j], 1);
                p1[hb][j] += __shfl_xor_sync(0xFFFFFFFFu, p1[hb][j], 2);
                p2[hb][j] += __shfl_xor_sync(0xFFFFFFFFu, p2[hb][j], 1);
                p2[hb][j] += __shfl_xor_sync(0xFFFFFFFFu, p2[hb][j], 2);
            }
        if (t == 0) {
            int r0 = block_row + warp_m * 32 + g;
#pragma unroll
            for (int hb = 0; hb < 2; hb++) {
                const int h = warp_n * 2 + hb;
#pragma unroll
                for (int j = 0; j < 4; j++) {
                    int row = r0 + (j >> 1) * 16 + (j & 1) * 8;
                    if (row < N_NODES) {
                        g_a1[row * HEADS + h] = p1[hb][j];
                        g_a2[row * HEADS + h] = p2[hb][j];
                    }
                }
            }
        }
    }
}

// ---------------- 3) CSR build: vectorized hist, 2-kernel scan, scatter ------
__global__ void hist_kernel(const int* __restrict__ dst) {
    int i4 = (blockIdx.x * blockDim.x + threadIdx.x) * 4;
    if (i4 + 4 <= N_EDGES) {
        int4 d = *reinterpret_cast<const int4*>(dst + i4);
        atomicAdd(&g_deg[d.x], 1);
        atomicAdd(&g_deg[d.y], 1);
        atomicAdd(&g_deg[d.z], 1);
        atomicAdd(&g_deg[d.w], 1);
    } else {
        for (int e = i4; e < N_EDGES; e++) atomicAdd(&g_deg[dst[e]], 1);
    }
}

__global__ __launch_bounds__(SCAN_TPB)
void scan1_kernel() {
    __shared__ int s[SCAN_TPB];
    int tid = threadIdx.x;
    int i = blockIdx.x * SCAN_TPB + tid;
    int v = 0;
    if (i < N_NODES) {
        v = g_deg[i];
        g_deg[i] = 0;              // self-reset for next graph replay
    }
    s[tid] = v;
    __syncthreads();
#pragma unroll
    for (int off = 1; off < SCAN_TPB; off <<= 1) {
        int t = (tid >= off) ? s[tid - off] : 0;
        __syncthreads();
        s[tid] += t;
        __syncthreads();
    }
    if (i < N_NODES) g_rowstart[i] = s[tid] - v;
    if (tid == SCAN_TPB - 1) g_bsum[blockIdx.x] = s[tid];
}

__global__ __launch_bounds__(SCAN_TPB)
void scan23_kernel() {
    __shared__ int s[SCAN_TPB];
    const int tid = threadIdx.x;
    const int bid = blockIdx.x;
    int v = (tid < bid && tid < SCAN_NB) ? g_bsum[tid] : 0;
    s[tid] = v;
    __syncthreads();
#pragma unroll
    for (int off = SCAN_TPB / 2; off > 0; off >>= 1) {
        if (tid < off) s[tid] += s[tid + off];
        __syncthreads();
    }
    const int offset = s[0];
    int i = bid * SCAN_TPB + tid;
    if (i < N_NODES) {
        int r = g_rowstart[i] + offset;
        g_rowstart[i] = r;
        g_cursor[i]   = r;
    }
    if (bid == 0 && tid == 0) g_rowstart[N_NODES] = N_EDGES;
}

__global__ void scatter_kernel(const int* __restrict__ src,
                               const int* __restrict__ dst) {
    int i4 = (blockIdx.x * blockDim.x + threadIdx.x) * 4;
    if (i4 + 4 <= N_EDGES) {
        int4 d = *reinterpret_cast<const int4*>(dst + i4);
        int4 sc = *reinterpret_cast<const int4*>(src + i4);
        g_csr_src[atomicAdd(&g_cursor[d.x], 1)] = sc.x;
        g_csr_src[atomicAdd(&g_cursor[d.y], 1)] = sc.y;
        g_csr_src[atomicAdd(&g_cursor[d.z], 1)] = sc.z;
        g_csr_src[atomicAdd(&g_cursor[d.w], 1)] = sc.w;
    } else {
        for (int e = i4; e < N_EDGES; e++)
            g_csr_src[atomicAdd(&g_cursor[dst[e]], 1)] = src[e];
    }
}

// ---------------- 4) warp-per-node fused GAT aggregation (no segment max) ----
__device__ __forceinline__ float lrelu(float x) {
    return (x > 0.0f) ? x : ALPHA * x;
}
__device__ __forceinline__ float wred_sum(float v) {
#pragma unroll
    for (int o = 16; o > 0; o >>= 1)
        v += __shfl_xor_sync(0xFFFFFFFFu, v, o);
    return v;
}
__device__ __forceinline__ void acc_row(float acc[8], float c, uint4 v) {
    const __half2* hp = reinterpret_cast<const __half2*>(&v);
#pragma unroll
    for (int k = 0; k < 4; k++) {
        float2 f = __half22float2(hp[k]);
        acc[2 * k]     += c * f.x;
        acc[2 * k + 1] += c * f.y;
    }
}

#define GAT_WPB 8   // warps per block

__global__ __launch_bounds__(GAT_WPB * 32)
void gat_warp_kernel(float* __restrict__ out)
{
    const int wid  = threadIdx.x >> 5;
    const int lane = threadIdx.x & 31;
    const int n    = blockIdx.x * GAT_WPB + wid;   // 50000 = 6250*8

    __shared__ float4 s_coef[GAT_WPB][32];
    __shared__ int    s_srcs[GAT_WPB][32];

    const int beg = g_rowstart[n];
    const int end = g_rowstart[n + 1];
    const int deg = end - beg;

    float4 a2v = __ldg(&reinterpret_cast<const float4*>(g_a2)[n]);

    float acc[8];
#pragma unroll
    for (int k = 0; k < 8; k++) acc[k] = 0.0f;
    const int hh = lane >> 3;          // lane owns cols [8*lane, 8*lane+8)

    if (deg <= 32) {
        // ---------- fast path: lane i owns edge i; direct exp, no max ----------
        int   s  = 0;
        float e0 = 0.f, e1 = 0.f, e2 = 0.f, e3 = 0.f;
        if (lane < deg) {
            s = __ldg(&g_csr_src[beg + lane]);
            float4 a1v = __ldg(&reinterpret_cast<const float4*>(g_a1)[s]);
            e0 = __expf(lrelu(a1v.x + a2v.x));
            e1 = __expf(lrelu(a1v.y + a2v.y));
            e2 = __expf(lrelu(a1v.z + a2v.z));
            e3 = __expf(lrelu(a1v.w + a2v.w));
        }
        float i0 = 1.0f / wred_sum(e0), i1 = 1.0f / wred_sum(e1);
        float i2 = 1.0f / wred_sum(e2), i3 = 1.0f / wred_sum(e3);
        if (lane < deg) {
            s_coef[wid][lane] = make_float4(e0 * i0, e1 * i1, e2 * i2, e3 * i3);
            s_srcs[wid][lane] = s;
        }
        __syncwarp();

        const float* cf = reinterpret_cast<const float*>(&s_coef[wid][0]);
        int li = 0;
        for (; li + 8 <= deg; li += 8) {           // 8 loads in flight
            uint4 v[8];
#pragma unroll
            for (int j = 0; j < 8; j++) {
                int sj = s_srcs[wid][li + j];
                v[j] = __ldg(reinterpret_cast<const uint4*>(
                                 g_fth + (size_t)sj * FDIM) + lane);
            }
#pragma unroll
            for (int j = 0; j < 8; j++)
                acc_row(acc, cf[(li + j) * 4 + hh], v[j]);
        }
        for (; li + 4 <= deg; li += 4) {
            uint4 v[4];
#pragma unroll
            for (int j = 0; j < 4; j++) {
                int sj = s_srcs[wid][li + j];
                v[j] = __ldg(reinterpret_cast<const uint4*>(
                                 g_fth + (size_t)sj * FDIM) + lane);
            }
#pragma unroll
            for (int j = 0; j < 4; j++)
                acc_row(acc, cf[(li + j) * 4 + hh], v[j]);
        }
        for (; li < deg; li++) {
            int sa = s_srcs[wid][li];
            uint4 va = __ldg(reinterpret_cast<const uint4*>(
                                 g_fth + (size_t)sa * FDIM) + lane);
            acc_row(acc, cf[li * 4 + hh], va);
        }
    } else {
        // ---------- slow path: strided sum pass + 32-edge coef tiles ----------
        float t0 = 0.f, t1 = 0.f, t2 = 0.f, t3 = 0.f;
        for (int i = beg + lane; i < end; i += 32) {
            int s = g_csr_src[i];
            float4 a1v = __ldg(&reinterpret_cast<const float4*>(g_a1)[s]);
            t0 += __expf(lrelu(a1v.x + a2v.x));
            t1 += __expf(lrelu(a1v.y + a2v.y));
            t2 += __expf(lrelu(a1v.z + a2v.z));
            t3 += __expf(lrelu(a1v.w + a2v.w));
        }
        float i0 = 1.0f / wred_sum(t0), i1 = 1.0f / wred_sum(t1);
        float i2 = 1.0f / wred_sum(t2), i3 = 1.0f / wred_sum(t3);

        const float* cf = reinterpret_cast<const float*>(&s_coef[wid][0]);
        for (int tb = beg; tb < end; tb += 32) {
            int cnt = min(32, end - tb);
            if (lane < cnt) {
                int s = __ldg(&g_csr_src[tb + lane]);
                float4 a1v = __ldg(&reinterpret_cast<const float4*>(g_a1)[s]);
                s_coef[wid][lane] = make_float4(
                    __expf(lrelu(a1v.x + a2v.x)) * i0,
                    __expf(lrelu(a1v.y + a2v.y)) * i1,
                    __expf(lrelu(a1v.z + a2v.z)) * i2,
                    __expf(lrelu(a1v.w + a2v.w)) * i3);
                s_srcs[wid][lane] = s;
            }
            __syncwarp();
            for (int li = 0; li < cnt; li++) {
                int sa = s_srcs[wid][li];
                uint4 va = __ldg(reinterpret_cast<const uint4*>(
                                     g_fth + (size_t)sa * FDIM) + lane);
                acc_row(acc, cf[li * 4 + hh], va);
            }
            __syncwarp();
        }
    }

    // ---- fused ELU + store ----
    float4 o0 = make_float4(
        acc[0] > 0.f ? acc[0] : expm1f(acc[0]),
        acc[1] > 0.f ? acc[1] : expm1f(acc[1]),
        acc[2] > 0.f ? acc[2] : expm1f(acc[2]),
        acc[3] > 0.f ? acc[3] : expm1f(acc[3]));
    float4 o1 = make_float4(
        acc[4] > 0.f ? acc[4] : expm1f(acc[4]),
        acc[5] > 0.f ? acc[5] : expm1f(acc[5]),
        acc[6] > 0.f ? acc[6] : expm1f(acc[6]),
        acc[7] > 0.f ? acc[7] : expm1f(acc[7]));
    float4* op = reinterpret_cast<float4*>(out + (size_t)n * FDIM + 8 * lane);
    op[0] = o0;
    op[1] = o1;
}

// ---------------- launch ------------------------------------------------------
extern "C" void kernel_launch(void* const* d_in, const int* in_sizes, int n_in,
                              void* d_out, int out_size)
{
    const float* feat   = (const float*)d_in[0];
    const int*   src    = (const int*)  d_in[1];
    const int*   dst    = (const int*)  d_in[2];
    const float* W      = (const float*)d_in[3];
    const float* attn_l = (const float*)d_in[4];
    const float* attn_r = (const float*)d_in[5];
    float* out = (float*)d_out;

    const int TPB = 256;
    const int E4  = (N_EDGES / 4 + TPB - 1) / TPB;

    static cudaStream_t s_side = nullptr;
    static cudaEvent_t  ev_fork = nullptr, ev_join = nullptr;
    if (s_side == nullptr) {
        cudaStreamCreateWithFlags(&s_side, cudaStreamNonBlocking);
        cudaEventCreateWithFlags(&ev_fork, cudaEventDisableTiming);
        cudaEventCreateWithFlags(&ev_join, cudaEventDisableTiming);
    }

    // ---- fork: side stream runs wconv+GEMM(+a1a2); main runs CSR build ----
    cudaEventRecord(ev_fork, 0);
    cudaStreamWaitEvent(s_side, ev_fork, 0);

    {
        wconv_kernel<<<(FDIM * IN_DIM / 4 + TPB - 1) / TPB, TPB, 0, s_side>>>(W);
        dim3 grid((N_NODES + GBM - 1) / GBM, 1);
        gemm_f16x2_kernel<<<grid, 256, 0, s_side>>>(feat, attn_l, attn_r);
    }

    hist_kernel<<<E4, TPB>>>(dst);
    scan1_kernel<<<SCAN_NB, SCAN_TPB>>>();
    scan23_kernel<<<SCAN_NB, SCAN_TPB>>>();
    scatter_kernel<<<E4, TPB>>>(src, dst);

    // ---- join ----
    cudaEventRecord(ev_join, s_side);
    cudaStreamWaitEvent(0, ev_join, 0);

    gat_warp_kernel<<<N_NODES / GAT_WPB, GAT_WPB * 32>>>(out);
}